// round 2
// baseline (speedup 1.0000x reference)
#include <cuda_runtime.h>
#include <cstddef>

#define VOCABP 50001
#define EMB    200
#define HID    128
#define BATCH  256
#define TSTEPS 500
#define NC     6
#define DENSE  64
#define NGATE  512   // 4*HID
#define HOFF   203   // row offset of h-part inside W [331, 512]

#define SMEM_COLS 416                 // gate columns cached in SMEM (13 warps)
#define GPITCH    516                 // gate staging pitch
#define SCAN_SMEM_BYTES ((HID*SMEM_COLS + 4*HID + 4*GPITCH) * 4)

// ---------------- scratch (no allocations allowed) ----------------
__device__ float g_tab[2ull * VOCABP * NGATE];   // projected vocab tables, ~205 MB
__device__ float g_captab[2 * 4 * NGATE];        // cap one-hot projection + bias
__device__ float g_hfinal[2 * BATCH * HID];      // final hidden states per direction

__device__ __forceinline__ float sigf(float x) { return 1.0f / (1.0f + __expf(-x)); }
__device__ __forceinline__ float tanh_fast(float x) {
    // 1 - 2/(e^{2x}+1); saturates correctly for |x| large
    return 1.0f - 2.0f / (__expf(2.0f * x) + 1.0f);
}

// ---------------- kernel 1: Tab[d] = word_emb @ W_d[0:200,:] ----------------
__global__ void __launch_bounds__(512) tab_kernel(const float* __restrict__ emb,
                                                  const float* __restrict__ Wfw,
                                                  const float* __restrict__ Wbw)
{
    __shared__ float es[EMB * 16];   // [k][r] transposed tile, 12.8 KB
    const int d  = blockIdx.y;
    const int v0 = blockIdx.x * 16;
    const float* __restrict__ W = d ? Wbw : Wfw;
    const int tid = threadIdx.x;

    for (int i = tid; i < 16 * EMB; i += 512) {
        int r = i / EMB, k = i % EMB;
        int v = v0 + r;
        es[k * 16 + r] = (v < VOCABP) ? emb[(size_t)v * EMB + k] : 0.0f;
    }
    __syncthreads();

    const int c = tid;   // gate column 0..511
    float acc[16];
#pragma unroll
    for (int r = 0; r < 16; r++) acc[r] = 0.0f;

#pragma unroll 4
    for (int k = 0; k < EMB; k++) {
        float w = __ldg(&W[k * NGATE + c]);
        const float4* e4 = (const float4*)&es[k * 16];
        float4 ea = e4[0], eb = e4[1], ec = e4[2], ed = e4[3];
        acc[0]  += ea.x * w;  acc[1]  += ea.y * w;  acc[2]  += ea.z * w;  acc[3]  += ea.w * w;
        acc[4]  += eb.x * w;  acc[5]  += eb.y * w;  acc[6]  += eb.z * w;  acc[7]  += eb.w * w;
        acc[8]  += ec.x * w;  acc[9]  += ec.y * w;  acc[10] += ec.z * w;  acc[11] += ec.w * w;
        acc[12] += ed.x * w;  acc[13] += ed.y * w;  acc[14] += ed.z * w;  acc[15] += ed.w * w;
    }

    float* out = &g_tab[((size_t)d * VOCABP + v0) * NGATE + c];
#pragma unroll
    for (int r = 0; r < 16; r++)
        if (v0 + r < VOCABP) out[(size_t)r * NGATE] = acc[r];
}

// ---------------- kernel 2: cap table (+ bias folded in) ----------------
__global__ void captab_kernel(const float* __restrict__ cemb,
                              const float* __restrict__ Wfw, const float* __restrict__ bfw,
                              const float* __restrict__ Wbw, const float* __restrict__ bbw)
{
    int idx = blockIdx.x * blockDim.x + threadIdx.x;
    if (idx >= 2 * 4 * NGATE) return;
    int d  = idx / (4 * NGATE);
    int ci = (idx / NGATE) & 3;
    int c  = idx % NGATE;
    const float* W = d ? Wbw : Wfw;
    const float* b = d ? bbw : bfw;
    float v = b[c];
#pragma unroll
    for (int j = 0; j < 3; j++) v += cemb[ci * 3 + j] * W[(EMB + j) * NGATE + c];
    g_captab[idx] = v;
}

// ---------------- kernel 3: the recurrent scan ----------------
// grid = 128 CTAs: blockIdx.x>>6 = direction, (blockIdx.x&63)*4 = first batch row
// 512 threads: thread c computes gate column c for 4 batch rows.
__global__ void __launch_bounds__(512, 1) scan_kernel(const int* __restrict__ words,
                                                      const int* __restrict__ caps,
                                                      const float* __restrict__ Wfw,
                                                      const float* __restrict__ Wbw)
{
    extern __shared__ float sm[];
    float* Ws  = sm;                       // [HID][SMEM_COLS]  208 KB
    float* h_s = Ws + HID * SMEM_COLS;     // [4][HID]
    float* g_s = h_s + 4 * HID;            // [4][GPITCH]

    const int tid = threadIdx.x;
    const int d   = blockIdx.x >> 6;
    const int b0  = (blockIdx.x & 63) * 4;
    const float* __restrict__ W = d ? Wbw : Wfw;

    // stage W_h columns [0, SMEM_COLS) into SMEM
    for (int i = tid; i < HID * SMEM_COLS; i += 512) {
        int k = i / SMEM_COLS, c = i % SMEM_COLS;
        Ws[i] = W[(HOFF + k) * NGATE + c];
    }
    if (tid < 4 * HID) h_s[tid] = 0.0f;

    const int r_id = tid >> 7;     // gate-update mapping: row
    const int u    = tid & 127;    // hidden unit
    float cst = 0.0f;              // cell state lives in registers
    float hh  = 0.0f;

    const int c = tid;             // gate column
    const float* __restrict__ tabd = &g_tab[(size_t)d * VOCABP * NGATE];
    const float* __restrict__ capd = &g_captab[d * 4 * NGATE];
    const float* __restrict__ wg   = &W[HOFF * NGATE + c];   // streamed columns

    __syncthreads();

    // prefetch indices for t = 0
    int widx[4], cidx[4];
    {
        int t0 = d ? (TSTEPS - 1) : 0;
#pragma unroll
        for (int r = 0; r < 4; r++) {
            widx[r] = __ldg(&words[(b0 + r) * TSTEPS + t0]);
            cidx[r] = __ldg(&caps [(b0 + r) * TSTEPS + t0]);
        }
    }

    for (int t = 0; t < TSTEPS; t++) {
        // issue x-gate gathers for this step early (consumed after the k-loop)
        float xg0 = __ldg(&tabd[(size_t)widx[0] * NGATE + c]) + __ldg(&capd[cidx[0] * NGATE + c]);
        float xg1 = __ldg(&tabd[(size_t)widx[1] * NGATE + c]) + __ldg(&capd[cidx[1] * NGATE + c]);
        float xg2 = __ldg(&tabd[(size_t)widx[2] * NGATE + c]) + __ldg(&capd[cidx[2] * NGATE + c]);
        float xg3 = __ldg(&tabd[(size_t)widx[3] * NGATE + c]) + __ldg(&capd[cidx[3] * NGATE + c]);

        // prefetch indices for next step
        if (t + 1 < TSTEPS) {
            int tt = d ? (TSTEPS - 2 - t) : (t + 1);
#pragma unroll
            for (int r = 0; r < 4; r++) {
                widx[r] = __ldg(&words[(b0 + r) * TSTEPS + tt]);
                cidx[r] = __ldg(&caps [(b0 + r) * TSTEPS + tt]);
            }
        }

        // recurrent GEMM: acc[r] = h[r] @ W_h[:, c]
        float a0 = 0.f, a1 = 0.f, a2 = 0.f, a3 = 0.f;
        if (c < SMEM_COLS) {
#pragma unroll 8
            for (int k = 0; k < HID; k += 4) {
                float4 h0 = *(const float4*)&h_s[0 * HID + k];
                float4 h1 = *(const float4*)&h_s[1 * HID + k];
                float4 h2 = *(const float4*)&h_s[2 * HID + k];
                float4 h3 = *(const float4*)&h_s[3 * HID + k];
                float w0 = Ws[(k + 0) * SMEM_COLS + c];
                float w1 = Ws[(k + 1) * SMEM_COLS + c];
                float w2 = Ws[(k + 2) * SMEM_COLS + c];
                float w3 = Ws[(k + 3) * SMEM_COLS + c];
                a0 += h0.x * w0; a1 += h1.x * w0; a2 += h2.x * w0; a3 += h3.x * w0;
                a0 += h0.y * w1; a1 += h1.y * w1; a2 += h2.y * w1; a3 += h3.y * w1;
                a0 += h0.z * w2; a1 += h1.z * w2; a2 += h2.z * w2; a3 += h3.z * w2;
                a0 += h0.w * w3; a1 += h1.w * w3; a2 += h2.w * w3; a3 += h3.w * w3;
            }
        } else {
            // columns [SMEM_COLS, 512): weights streamed from L2 each step
#pragma unroll 8
            for (int k = 0; k < HID; k += 4) {
                float w0 = __ldg(&wg[(k + 0) * NGATE]);
                float w1 = __ldg(&wg[(k + 1) * NGATE]);
                float w2 = __ldg(&wg[(k + 2) * NGATE]);
                float w3 = __ldg(&wg[(k + 3) * NGATE]);
                float4 h0 = *(const float4*)&h_s[0 * HID + k];
                float4 h1 = *(const float4*)&h_s[1 * HID + k];
                float4 h2 = *(const float4*)&h_s[2 * HID + k];
                float4 h3 = *(const float4*)&h_s[3 * HID + k];
                a0 += h0.x * w0; a1 += h1.x * w0; a2 += h2.x * w0; a3 += h3.x * w0;
                a0 += h0.y * w1; a1 += h1.y * w1; a2 += h2.y * w1; a3 += h3.y * w1;
                a0 += h0.z * w2; a1 += h1.z * w2; a2 += h2.z * w2; a3 += h3.z * w2;
                a0 += h0.w * w3; a1 += h1.w * w3; a2 += h2.w * w3; a3 += h3.w * w3;
            }
        }
        a0 += xg0; a1 += xg1; a2 += xg2; a3 += xg3;

        g_s[0 * GPITCH + c] = a0;
        g_s[1 * GPITCH + c] = a1;
        g_s[2 * GPITCH + c] = a2;
        g_s[3 * GPITCH + c] = a3;
        __syncthreads();

        // gate update: thread (r_id, u) owns one (row, hidden-unit)
        {
            float gi = g_s[r_id * GPITCH + u];
            float gj = g_s[r_id * GPITCH + u + HID];
            float gf = g_s[r_id * GPITCH + u + 2 * HID];
            float go = g_s[r_id * GPITCH + u + 3 * HID];
            cst = sigf(gf + 1.0f) * cst + sigf(gi) * tanh_fast(gj);
            hh  = sigf(go) * tanh_fast(cst);
            h_s[r_id * HID + u] = hh;
        }
        __syncthreads();
    }

    g_hfinal[((d * BATCH) + (b0 + r_id)) * HID + u] = hh;
}

// ---------------- kernel 4: dense head ----------------
__global__ void __launch_bounds__(DENSE) dense_kernel(const float* __restrict__ W1,
                                                      const float* __restrict__ b1,
                                                      const float* __restrict__ W2,
                                                      const float* __restrict__ b2,
                                                      float* __restrict__ out)
{
    __shared__ float d1[DENSE];
    const int b = blockIdx.x, j = threadIdx.x;
    const float* hf0 = &g_hfinal[b * HID];            // forward last
    const float* hf1 = &g_hfinal[(BATCH + b) * HID];  // backward "first"
    float acc = b1[j];
#pragma unroll 4
    for (int k = 0; k < HID; k++) acc += hf0[k] * W1[k * DENSE + j];
#pragma unroll 4
    for (int k = 0; k < HID; k++) acc += hf1[k] * W1[(HID + k) * DENSE + j];
    d1[j] = (acc > 0.0f) ? acc : (__expf(acc) - 1.0f);   // elu
    __syncthreads();
    if (j < NC) {
        float a = b2[j];
#pragma unroll
        for (int k = 0; k < DENSE; k++) a += d1[k] * W2[k * NC + j];
        out[b * NC + j] = 1.0f / (1.0f + __expf(-a));    // sigmoid
    }
}

// ---------------- launch ----------------
extern "C" void kernel_launch(void* const* d_in, const int* in_sizes, int n_in,
                              void* d_out, int out_size)
{
    const int*   words = (const int*)  d_in[0];
    const int*   caps  = (const int*)  d_in[1];
    const float* emb   = (const float*)d_in[2];
    const float* cemb  = (const float*)d_in[3];
    const float* Wfw   = (const float*)d_in[4];
    const float* bfw   = (const float*)d_in[5];
    const float* Wbw   = (const float*)d_in[6];
    const float* bbw   = (const float*)d_in[7];
    const float* W1    = (const float*)d_in[8];
    const float* b1    = (const float*)d_in[9];
    const float* W2    = (const float*)d_in[10];
    const float* b2    = (const float*)d_in[11];
    float* out = (float*)d_out;

    cudaFuncSetAttribute(scan_kernel, cudaFuncAttributeMaxDynamicSharedMemorySize,
                         SCAN_SMEM_BYTES);

    tab_kernel<<<dim3((VOCABP + 15) / 16, 2), 512>>>(emb, Wfw, Wbw);
    captab_kernel<<<8, 512>>>(cemb, Wfw, bfw, Wbw, bbw);
    scan_kernel<<<128, 512, SCAN_SMEM_BYTES>>>(words, caps, Wfw, Wbw);
    dense_kernel<<<BATCH, DENSE>>>(W1, b1, W2, b2, out);
}

// round 3
// speedup vs baseline: 1.0005x; 1.0005x over previous
#include <cuda_runtime.h>
#include <cstddef>

#define VOCABP 50001
#define EMB    200
#define HID    128
#define BATCH  256
#define TSTEPS 500
#define NC     6
#define DENSE  64
#define NGATE  512   // 4*HID
#define HOFF   203   // row offset of h-part inside W [331, 512]

#define SMEM_COLS 416                 // gate columns cached in SMEM (13 warps)
#define GPITCH    516                 // gate staging pitch
#define SCAN_SMEM_BYTES ((HID*SMEM_COLS + 4*HID + 4*GPITCH) * 4)

// ---------------- scratch (no allocations allowed) ----------------
__device__ float g_tab[2ull * VOCABP * NGATE];   // projected vocab tables, ~205 MB
__device__ float g_captab[2 * 4 * NGATE];        // cap one-hot projection + bias
__device__ float g_hfinal[2 * BATCH * HID];      // final hidden states per direction

__device__ __forceinline__ float sigf(float x) { return 1.0f / (1.0f + __expf(-x)); }
__device__ __forceinline__ float tanh_fast(float x) {
    // 1 - 2/(e^{2x}+1); saturates correctly for |x| large
    return 1.0f - 2.0f / (__expf(2.0f * x) + 1.0f);
}

// ---------------- kernel 1: Tab[d] = word_emb @ W_d[0:200,:] ----------------
__global__ void __launch_bounds__(512) tab_kernel(const float* __restrict__ emb,
                                                  const float* __restrict__ Wfw,
                                                  const float* __restrict__ Wbw)
{
    __shared__ float es[EMB * 16];   // [k][r] transposed tile, 12.8 KB
    const int d  = blockIdx.y;
    const int v0 = blockIdx.x * 16;
    const float* __restrict__ W = d ? Wbw : Wfw;
    const int tid = threadIdx.x;

    for (int i = tid; i < 16 * EMB; i += 512) {
        int r = i / EMB, k = i % EMB;
        int v = v0 + r;
        es[k * 16 + r] = (v < VOCABP) ? emb[(size_t)v * EMB + k] : 0.0f;
    }
    __syncthreads();

    const int c = tid;   // gate column 0..511
    float acc[16];
#pragma unroll
    for (int r = 0; r < 16; r++) acc[r] = 0.0f;

#pragma unroll 4
    for (int k = 0; k < EMB; k++) {
        float w = __ldg(&W[k * NGATE + c]);
        const float4* e4 = (const float4*)&es[k * 16];
        float4 ea = e4[0], eb = e4[1], ec = e4[2], ed = e4[3];
        acc[0]  += ea.x * w;  acc[1]  += ea.y * w;  acc[2]  += ea.z * w;  acc[3]  += ea.w * w;
        acc[4]  += eb.x * w;  acc[5]  += eb.y * w;  acc[6]  += eb.z * w;  acc[7]  += eb.w * w;
        acc[8]  += ec.x * w;  acc[9]  += ec.y * w;  acc[10] += ec.z * w;  acc[11] += ec.w * w;
        acc[12] += ed.x * w;  acc[13] += ed.y * w;  acc[14] += ed.z * w;  acc[15] += ed.w * w;
    }

    float* out = &g_tab[((size_t)d * VOCABP + v0) * NGATE + c];
#pragma unroll
    for (int r = 0; r < 16; r++)
        if (v0 + r < VOCABP) out[(size_t)r * NGATE] = acc[r];
}

// ---------------- kernel 2: cap table (+ bias folded in) ----------------
__global__ void captab_kernel(const float* __restrict__ cemb,
                              const float* __restrict__ Wfw, const float* __restrict__ bfw,
                              const float* __restrict__ Wbw, const float* __restrict__ bbw)
{
    int idx = blockIdx.x * blockDim.x + threadIdx.x;
    if (idx >= 2 * 4 * NGATE) return;
    int d  = idx / (4 * NGATE);
    int ci = (idx / NGATE) & 3;
    int c  = idx % NGATE;
    const float* W = d ? Wbw : Wfw;
    const float* b = d ? bbw : bfw;
    float v = b[c];
#pragma unroll
    for (int j = 0; j < 3; j++) v += cemb[ci * 3 + j] * W[(EMB + j) * NGATE + c];
    g_captab[idx] = v;
}

// ---------------- kernel 3: the recurrent scan ----------------
// grid = 128 CTAs: blockIdx.x>>6 = direction, (blockIdx.x&63)*4 = first batch row
// 512 threads: thread c computes gate column c for 4 batch rows.
__global__ void __launch_bounds__(512, 1) scan_kernel(const int* __restrict__ words,
                                                      const int* __restrict__ caps,
                                                      const float* __restrict__ Wfw,
                                                      const float* __restrict__ Wbw)
{
    extern __shared__ float sm[];
    float* Ws  = sm;                       // [HID][SMEM_COLS]  208 KB
    float* h_s = Ws + HID * SMEM_COLS;     // [4][HID]
    float* g_s = h_s + 4 * HID;            // [4][GPITCH]

    const int tid = threadIdx.x;
    const int d   = blockIdx.x >> 6;
    const int b0  = (blockIdx.x & 63) * 4;
    const float* __restrict__ W = d ? Wbw : Wfw;

    // stage W_h columns [0, SMEM_COLS) into SMEM
    for (int i = tid; i < HID * SMEM_COLS; i += 512) {
        int k = i / SMEM_COLS, c = i % SMEM_COLS;
        Ws[i] = W[(HOFF + k) * NGATE + c];
    }
    if (tid < 4 * HID) h_s[tid] = 0.0f;

    const int r_id = tid >> 7;     // gate-update mapping: row
    const int u    = tid & 127;    // hidden unit
    float cst = 0.0f;              // cell state lives in registers
    float hh  = 0.0f;

    const int c = tid;             // gate column
    const float* __restrict__ tabd = &g_tab[(size_t)d * VOCABP * NGATE];
    const float* __restrict__ capd = &g_captab[d * 4 * NGATE];
    const float* __restrict__ wg   = &W[HOFF * NGATE + c];   // streamed columns

    __syncthreads();

    // prefetch indices for t = 0
    int widx[4], cidx[4];
    {
        int t0 = d ? (TSTEPS - 1) : 0;
#pragma unroll
        for (int r = 0; r < 4; r++) {
            widx[r] = __ldg(&words[(b0 + r) * TSTEPS + t0]);
            cidx[r] = __ldg(&caps [(b0 + r) * TSTEPS + t0]);
        }
    }

    for (int t = 0; t < TSTEPS; t++) {
        // issue x-gate gathers for this step early (consumed after the k-loop)
        float xg0 = __ldg(&tabd[(size_t)widx[0] * NGATE + c]) + __ldg(&capd[cidx[0] * NGATE + c]);
        float xg1 = __ldg(&tabd[(size_t)widx[1] * NGATE + c]) + __ldg(&capd[cidx[1] * NGATE + c]);
        float xg2 = __ldg(&tabd[(size_t)widx[2] * NGATE + c]) + __ldg(&capd[cidx[2] * NGATE + c]);
        float xg3 = __ldg(&tabd[(size_t)widx[3] * NGATE + c]) + __ldg(&capd[cidx[3] * NGATE + c]);

        // prefetch indices for next step
        if (t + 1 < TSTEPS) {
            int tt = d ? (TSTEPS - 2 - t) : (t + 1);
#pragma unroll
            for (int r = 0; r < 4; r++) {
                widx[r] = __ldg(&words[(b0 + r) * TSTEPS + tt]);
                cidx[r] = __ldg(&caps [(b0 + r) * TSTEPS + tt]);
            }
        }

        // recurrent GEMM: acc[r] = h[r] @ W_h[:, c]
        float a0 = 0.f, a1 = 0.f, a2 = 0.f, a3 = 0.f;
        if (c < SMEM_COLS) {
#pragma unroll 8
            for (int k = 0; k < HID; k += 4) {
                float4 h0 = *(const float4*)&h_s[0 * HID + k];
                float4 h1 = *(const float4*)&h_s[1 * HID + k];
                float4 h2 = *(const float4*)&h_s[2 * HID + k];
                float4 h3 = *(const float4*)&h_s[3 * HID + k];
                float w0 = Ws[(k + 0) * SMEM_COLS + c];
                float w1 = Ws[(k + 1) * SMEM_COLS + c];
                float w2 = Ws[(k + 2) * SMEM_COLS + c];
                float w3 = Ws[(k + 3) * SMEM_COLS + c];
                a0 += h0.x * w0; a1 += h1.x * w0; a2 += h2.x * w0; a3 += h3.x * w0;
                a0 += h0.y * w1; a1 += h1.y * w1; a2 += h2.y * w1; a3 += h3.y * w1;
                a0 += h0.z * w2; a1 += h1.z * w2; a2 += h2.z * w2; a3 += h3.z * w2;
                a0 += h0.w * w3; a1 += h1.w * w3; a2 += h2.w * w3; a3 += h3.w * w3;
            }
        } else {
            // columns [SMEM_COLS, 512): weights streamed from L2 each step
#pragma unroll 8
            for (int k = 0; k < HID; k += 4) {
                float w0 = __ldg(&wg[(k + 0) * NGATE]);
                float w1 = __ldg(&wg[(k + 1) * NGATE]);
                float w2 = __ldg(&wg[(k + 2) * NGATE]);
                float w3 = __ldg(&wg[(k + 3) * NGATE]);
                float4 h0 = *(const float4*)&h_s[0 * HID + k];
                float4 h1 = *(const float4*)&h_s[1 * HID + k];
                float4 h2 = *(const float4*)&h_s[2 * HID + k];
                float4 h3 = *(const float4*)&h_s[3 * HID + k];
                a0 += h0.x * w0; a1 += h1.x * w0; a2 += h2.x * w0; a3 += h3.x * w0;
                a0 += h0.y * w1; a1 += h1.y * w1; a2 += h2.y * w1; a3 += h3.y * w1;
                a0 += h0.z * w2; a1 += h1.z * w2; a2 += h2.z * w2; a3 += h3.z * w2;
                a0 += h0.w * w3; a1 += h1.w * w3; a2 += h2.w * w3; a3 += h3.w * w3;
            }
        }
        a0 += xg0; a1 += xg1; a2 += xg2; a3 += xg3;

        g_s[0 * GPITCH + c] = a0;
        g_s[1 * GPITCH + c] = a1;
        g_s[2 * GPITCH + c] = a2;
        g_s[3 * GPITCH + c] = a3;
        __syncthreads();

        // gate update: thread (r_id, u) owns one (row, hidden-unit)
        {
            float gi = g_s[r_id * GPITCH + u];
            float gj = g_s[r_id * GPITCH + u + HID];
            float gf = g_s[r_id * GPITCH + u + 2 * HID];
            float go = g_s[r_id * GPITCH + u + 3 * HID];
            cst = sigf(gf + 1.0f) * cst + sigf(gi) * tanh_fast(gj);
            hh  = sigf(go) * tanh_fast(cst);
            h_s[r_id * HID + u] = hh;
        }
        __syncthreads();
    }

    g_hfinal[((d * BATCH) + (b0 + r_id)) * HID + u] = hh;
}

// ---------------- kernel 4: dense head ----------------
__global__ void __launch_bounds__(DENSE) dense_kernel(const float* __restrict__ W1,
                                                      const float* __restrict__ b1,
                                                      const float* __restrict__ W2,
                                                      const float* __restrict__ b2,
                                                      float* __restrict__ out)
{
    __shared__ float d1[DENSE];
    const int b = blockIdx.x, j = threadIdx.x;
    const float* hf0 = &g_hfinal[b * HID];            // forward last
    const float* hf1 = &g_hfinal[(BATCH + b) * HID];  // backward "first"
    float acc = b1[j];
#pragma unroll 4
    for (int k = 0; k < HID; k++) acc += hf0[k] * W1[k * DENSE + j];
#pragma unroll 4
    for (int k = 0; k < HID; k++) acc += hf1[k] * W1[(HID + k) * DENSE + j];
    d1[j] = (acc > 0.0f) ? acc : (__expf(acc) - 1.0f);   // elu
    __syncthreads();
    if (j < NC) {
        float a = b2[j];
#pragma unroll
        for (int k = 0; k < DENSE; k++) a += d1[k] * W2[k * NC + j];
        out[b * NC + j] = 1.0f / (1.0f + __expf(-a));    // sigmoid
    }
}

// ---------------- launch ----------------
extern "C" void kernel_launch(void* const* d_in, const int* in_sizes, int n_in,
                              void* d_out, int out_size)
{
    const int*   words = (const int*)  d_in[0];
    const int*   caps  = (const int*)  d_in[1];
    const float* emb   = (const float*)d_in[2];
    const float* cemb  = (const float*)d_in[3];
    const float* Wfw   = (const float*)d_in[4];
    const float* bfw   = (const float*)d_in[5];
    const float* Wbw   = (const float*)d_in[6];
    const float* bbw   = (const float*)d_in[7];
    const float* W1    = (const float*)d_in[8];
    const float* b1    = (const float*)d_in[9];
    const float* W2    = (const float*)d_in[10];
    const float* b2    = (const float*)d_in[11];
    float* out = (float*)d_out;

    cudaFuncSetAttribute(scan_kernel, cudaFuncAttributeMaxDynamicSharedMemorySize,
                         SCAN_SMEM_BYTES);

    tab_kernel<<<dim3((VOCABP + 15) / 16, 2), 512>>>(emb, Wfw, Wbw);
    captab_kernel<<<8, 512>>>(cemb, Wfw, bfw, Wbw, bbw);
    scan_kernel<<<128, 512, SCAN_SMEM_BYTES>>>(words, caps, Wfw, Wbw);
    dense_kernel<<<BATCH, DENSE>>>(W1, b1, W2, b2, out);
}